// round 1
// baseline (speedup 1.0000x reference)
#include <cuda_runtime.h>
#include <math.h>

#define D    128
#define NVV  4000
#define NLIT 8000
#define NCLS 16000
#define GD   512          // 4*D
#define NNZ_MAX 480000

// ---------------- persistent scratch (device globals; allocation-free) ------
__device__ float g_L[NLIT * D];
__device__ float g_hL[NLIT * D];
__device__ float g_hC[NCLS * D];
__device__ float g_Cs[NCLS * D];
__device__ float g_pre[NCLS * D];     // LC_pre (NLIT rows) or CL_pre (NCLS rows)
__device__ float g_msgs[NCLS * D];    // clause msgs (NCLS rows) or literal msgs (NLIT rows)
__device__ float g_gates[NCLS * GD];  // gate pre-activations
__device__ float g_WC[GD * 2 * D];    // [Wih_C | Whh_C], row-major (512, 256)
__device__ float g_WL[GD * 3 * D];    // [Wih_L | Whh_L], row-major (512, 384)
__device__ float g_bC[GD];
__device__ float g_bL[GD];

__device__ int g_lit_ptr[NLIT + 1];
__device__ int g_cls_ptr[NCLS + 1];
__device__ int g_lit_idx[NNZ_MAX];
__device__ int g_cls_idx[NNZ_MAX];
__device__ int g_lit_cnt[NLIT];
__device__ int g_cls_cnt[NCLS];
__device__ int g_pair_l[NNZ_MAX];
__device__ int g_pair_c[NNZ_MAX];
__device__ int g_nnz[1];

// ---------------- small utility kernels ------------------------------------
__global__ void copy_f(float* __restrict__ dst, const float* __restrict__ src, int n) {
    int stride = gridDim.x * blockDim.x;
    for (int i = blockIdx.x * blockDim.x + threadIdx.x; i < n; i += stride)
        dst[i] = src[i];
}

__global__ void zero_i(int* __restrict__ p, int n) {
    int stride = gridDim.x * blockDim.x;
    for (int i = blockIdx.x * blockDim.x + threadIdx.x; i < n; i += stride)
        p[i] = 0;
}

__global__ void init_state(const float* __restrict__ L, const float* __restrict__ hL,
                           const float* __restrict__ hC) {
    int stride = gridDim.x * blockDim.x;
    for (int i = blockIdx.x * blockDim.x + threadIdx.x; i < NCLS * D; i += stride) {
        if (i < NLIT * D) { g_L[i] = L[i]; g_hL[i] = hL[i]; }
        g_hC[i] = hC[i];
    }
}

__global__ void prep_weights(const float* __restrict__ WihC, const float* __restrict__ WhhC,
                             const float* __restrict__ bihC, const float* __restrict__ bhhC,
                             const float* __restrict__ WihL, const float* __restrict__ WhhL,
                             const float* __restrict__ bihL, const float* __restrict__ bhhL) {
    int stride = gridDim.x * blockDim.x;
    int tid0 = blockIdx.x * blockDim.x + threadIdx.x;
    for (int t = tid0; t < GD * 2 * D; t += stride) {
        int j = t / (2 * D), k = t % (2 * D);
        g_WC[t] = (k < D) ? WihC[j * D + k] : WhhC[j * D + (k - D)];
    }
    for (int t = tid0; t < GD * 3 * D; t += stride) {
        int j = t / (3 * D), k = t % (3 * D);
        g_WL[t] = (k < 2 * D) ? WihL[j * 2 * D + k] : WhhL[j * D + (k - 2 * D)];
    }
    for (int t = tid0; t < GD; t += stride) {
        g_bC[t] = bihC[t] + bhhC[t];
        g_bL[t] = bihL[t] + bhhL[t];
    }
}

// ---------------- CSR build -------------------------------------------------
// One pass over M (row-major NLIT x NCLS). Records (l,c) pairs (warp-aggregated
// global cursor) and per-row/per-col counts.
__global__ void build_pairs(const float* __restrict__ M) {
    int l = blockIdx.y;
    const float4* row = (const float4*)(M + (size_t)l * NCLS);
    const int total4 = NCLS / 4;  // 4000
    int lane = threadIdx.x & 31;
    int stride = gridDim.x * blockDim.x;
    int row_count = 0;

    for (int i = blockIdx.x * blockDim.x + threadIdx.x;; i += stride) {
        bool inb = i < total4;
        if (__ballot_sync(0xffffffffu, inb) == 0) break;
        float4 v = inb ? row[i] : make_float4(0.f, 0.f, 0.f, 0.f);
        float vv[4] = {v.x, v.y, v.z, v.w};
#pragma unroll
        for (int j = 0; j < 4; j++) {
            bool pred = vv[j] > 0.5f;
            unsigned act = __ballot_sync(0xffffffffu, pred);
            int tot = __popc(act);
            if (pred) {
                int rank = __popc(act & ((1u << lane) - 1u));
                int leader = __ffs(act) - 1;
                int base = 0;
                if (lane == leader) base = atomicAdd(&g_nnz[0], tot);
                base = __shfl_sync(act, base, leader);
                int p = base + rank;
                int c = i * 4 + j;
                if (p < NNZ_MAX) { g_pair_l[p] = l; g_pair_c[p] = c; }
                atomicAdd(&g_cls_cnt[c], 1);
            }
            row_count += tot;   // uniform across warp
        }
    }
    if (lane == 0 && row_count) atomicAdd(&g_lit_cnt[l], row_count);
}

// Single-block exclusive scan (n up to NCLS)
__global__ void scan_excl(const int* __restrict__ cnt, int* __restrict__ ptr, int n) {
    const int T = 1024;
    __shared__ int part[T];
    int t = threadIdx.x;
    int chunk = (n + T - 1) / T;
    int s0 = t * chunk;
    int s1 = min(n, s0 + chunk);
    int s = 0;
    for (int i = s0; i < s1; i++) s += cnt[i];
    part[t] = s;
    __syncthreads();
    if (t == 0) {
        int run = 0;
        for (int i = 0; i < T; i++) { int v = part[i]; part[i] = run; run += v; }
        ptr[n] = run;
    }
    __syncthreads();
    int run = part[t];
    for (int i = s0; i < s1; i++) { ptr[i] = run; run += cnt[i]; }
}

__global__ void fill_csr() {
    int nnz = g_nnz[0];
    if (nnz > NNZ_MAX) nnz = NNZ_MAX;
    int stride = gridDim.x * blockDim.x;
    for (int i = blockIdx.x * blockDim.x + threadIdx.x; i < nnz; i += stride) {
        int l = g_pair_l[i], c = g_pair_c[i];
        int p = g_lit_ptr[l] + atomicAdd(&g_lit_cnt[l], 1);
        g_lit_idx[p] = c;
        int q = g_cls_ptr[c] + atomicAdd(&g_cls_cnt[c], 1);
        g_cls_idx[q] = l;
    }
}

// ---------------- SpMM (gather) --------------------------------------------
// dst[row,:] = sum over idx in [ptr[row], ptr[row+1]) of src[idx,:]
__global__ void spmm_gather(const int* __restrict__ ptr, const int* __restrict__ idx,
                            const float* __restrict__ src, float* __restrict__ dst) {
    int row = blockIdx.x;
    int d = threadIdx.x;  // 128
    int s = ptr[row], e = ptr[row + 1];
    float acc = 0.f;
    for (int j = s; j < e; j++) acc += __ldg(&src[(size_t)idx[j] * D + d]);
    dst[(size_t)row * D + d] = acc;
}

// ---------------- GEMM: C[M x N] = catA[M x K] * B[N x K]^T + bias ---------
#define BM 64
#define BN 64
#define BK 16

__global__ void __launch_bounds__(256) gemm_tn(
    const float* __restrict__ A0, const float* __restrict__ A1, const float* __restrict__ A2,
    int K0, int K1, int K2,
    const float* __restrict__ B, const float* __restrict__ bias,
    float* __restrict__ C, int N, int K) {
    __shared__ float As[BK][BM];
    __shared__ float Bs[BK][BN];
    int tid = threadIdx.x;
    int tx = tid & 15, ty = tid >> 4;
    int m0 = blockIdx.y * BM, n0 = blockIdx.x * BN;
    int r = tid >> 2;
    int cc = (tid & 3) * 4;

    float acc[4][4];
#pragma unroll
    for (int i = 0; i < 4; i++)
#pragma unroll
        for (int j = 0; j < 4; j++) acc[i][j] = 0.f;

    for (int k0 = 0; k0 < K; k0 += BK) {
        const float* Aseg;
        int segK, ko;
        if (k0 < K0)            { Aseg = A0; segK = K0; ko = k0; }
        else if (k0 < K0 + K1)  { Aseg = A1; segK = K1; ko = k0 - K0; }
        else                    { Aseg = A2; segK = K2; ko = k0 - K0 - K1; }

        float4 av = *(const float4*)(Aseg + (size_t)(m0 + r) * segK + ko + cc);
        As[cc + 0][r] = av.x; As[cc + 1][r] = av.y; As[cc + 2][r] = av.z; As[cc + 3][r] = av.w;
        float4 bv = *(const float4*)(B + (size_t)(n0 + r) * K + k0 + cc);
        Bs[cc + 0][r] = bv.x; Bs[cc + 1][r] = bv.y; Bs[cc + 2][r] = bv.z; Bs[cc + 3][r] = bv.w;
        __syncthreads();

#pragma unroll
        for (int k = 0; k < BK; k++) {
            float4 a = *(const float4*)&As[k][ty * 4];
            float4 b = *(const float4*)&Bs[k][tx * 4];
            float a4[4] = {a.x, a.y, a.z, a.w};
            float b4[4] = {b.x, b.y, b.z, b.w};
#pragma unroll
            for (int i = 0; i < 4; i++)
#pragma unroll
                for (int j = 0; j < 4; j++) acc[i][j] += a4[i] * b4[j];
        }
        __syncthreads();
    }

    float bj[4];
#pragma unroll
    for (int j = 0; j < 4; j++) bj[j] = bias[n0 + tx * 4 + j];
#pragma unroll
    for (int i = 0; i < 4; i++) {
        int m = m0 + ty * 4 + i;
        float4 o;
        o.x = acc[i][0] + bj[0];
        o.y = acc[i][1] + bj[1];
        o.z = acc[i][2] + bj[2];
        o.w = acc[i][3] + bj[3];
        *(float4*)(C + (size_t)m * N + n0 + tx * 4) = o;
    }
}

// ---------------- LSTM pointwise -------------------------------------------
__device__ __forceinline__ float sigm(float x) { return 1.f / (1.f + expf(-x)); }

// gates: (rows, 512) [i|f|g|o]; c_state in/out (<- c_new); h_out <- h_new
__global__ void lstm_update(const float* __restrict__ gates, float* __restrict__ c_state,
                            float* __restrict__ h_out, int rows) {
    int n = rows * D;
    int stride = gridDim.x * blockDim.x;
    for (int i = blockIdx.x * blockDim.x + threadIdx.x; i < n; i += stride) {
        int row = i >> 7, d = i & 127;
        const float* gr = gates + (size_t)row * GD;
        float ig = gr[d], fg = gr[D + d], gg = gr[2 * D + d], og = gr[3 * D + d];
        float c = c_state[i];
        float c_new = sigm(fg) * c + sigm(ig) * tanhf(gg);
        c_state[i] = c_new;
        h_out[i] = sigm(og) * tanhf(c_new);
    }
}

// ---------------- driver ----------------------------------------------------
extern "C" void kernel_launch(void* const* d_in, const int* in_sizes, int n_in,
                              void* d_out, int out_size) {
    const float* L_state  = (const float*)d_in[0];
    // d_in[1] = C_state (unused by reference)
    const float* hidden_L = (const float*)d_in[2];
    const float* hidden_C = (const float*)d_in[3];
    const float* Mmat     = (const float*)d_in[4];
    // d_in[5] = n_vars (flip() is identity; unused)
    const float* W_lc = (const float*)d_in[6];
    const float* b_lc = (const float*)d_in[7];
    const float* W_cl = (const float*)d_in[8];
    const float* b_cl = (const float*)d_in[9];
    const float* WihC = (const float*)d_in[10];
    const float* WhhC = (const float*)d_in[11];
    const float* bihC = (const float*)d_in[12];
    const float* bhhC = (const float*)d_in[13];
    const float* WihL = (const float*)d_in[14];
    const float* WhhL = (const float*)d_in[15];
    const float* bihL = (const float*)d_in[16];
    const float* bhhL = (const float*)d_in[17];
    float* out = (float*)d_out;

    float *pL, *phL, *phC, *pCs, *pPre, *pMsgs, *pGates, *pWC, *pWL, *pbC, *pbL;
    int *pLitPtr, *pClsPtr, *pLitIdx, *pClsIdx, *pLitCnt, *pClsCnt, *pNnz;
    cudaGetSymbolAddress((void**)&pL, g_L);
    cudaGetSymbolAddress((void**)&phL, g_hL);
    cudaGetSymbolAddress((void**)&phC, g_hC);
    cudaGetSymbolAddress((void**)&pCs, g_Cs);
    cudaGetSymbolAddress((void**)&pPre, g_pre);
    cudaGetSymbolAddress((void**)&pMsgs, g_msgs);
    cudaGetSymbolAddress((void**)&pGates, g_gates);
    cudaGetSymbolAddress((void**)&pWC, g_WC);
    cudaGetSymbolAddress((void**)&pWL, g_WL);
    cudaGetSymbolAddress((void**)&pbC, g_bC);
    cudaGetSymbolAddress((void**)&pbL, g_bL);
    cudaGetSymbolAddress((void**)&pLitPtr, g_lit_ptr);
    cudaGetSymbolAddress((void**)&pClsPtr, g_cls_ptr);
    cudaGetSymbolAddress((void**)&pLitIdx, g_lit_idx);
    cudaGetSymbolAddress((void**)&pClsIdx, g_cls_idx);
    cudaGetSymbolAddress((void**)&pLitCnt, g_lit_cnt);
    cudaGetSymbolAddress((void**)&pClsCnt, g_cls_cnt);
    cudaGetSymbolAddress((void**)&pNnz, g_nnz);

    // init persistent state + fused weights
    init_state<<<2048, 256>>>(L_state, hidden_L, hidden_C);
    prep_weights<<<512, 256>>>(WihC, WhhC, bihC, bhhC, WihL, WhhL, bihL, bhhL);

    // build CSR (both orientations) from dense M
    zero_i<<<64, 256>>>(pLitCnt, NLIT);
    zero_i<<<64, 256>>>(pClsCnt, NCLS);
    zero_i<<<1, 32>>>(pNnz, 1);
    build_pairs<<<dim3(4, NLIT), 256>>>(Mmat);
    scan_excl<<<1, 1024>>>(pLitCnt, pLitPtr, NLIT);
    scan_excl<<<1, 1024>>>(pClsCnt, pClsPtr, NCLS);
    zero_i<<<64, 256>>>(pLitCnt, NLIT);
    zero_i<<<64, 256>>>(pClsCnt, NCLS);
    fill_csr<<<512, 256>>>();

    for (int t = 0; t < 8; t++) {
        // LC_pre = L @ W_lc^T + b_lc                         (NLIT x 128)
        gemm_tn<<<dim3(D / BN, NLIT / BM), 256>>>(pL, nullptr, nullptr, D, 0, 0,
                                                  W_lc, b_lc, pPre, D, D);
        // LC_msgs[c] = sum_{l in clause c} LC_pre[l]         (NCLS x 128)
        spmm_gather<<<NCLS, 128>>>(pClsPtr, pClsIdx, pPre, pMsgs);
        // gates_C = [msgs|hC] @ [WihC|WhhC]^T + (bih+bhh)    (NCLS x 512)
        gemm_tn<<<dim3(GD / BN, NCLS / BM), 256>>>(pMsgs, phC, nullptr, D, D, 0,
                                                   pWC, pbC, pGates, GD, 2 * D);
        // hC <- c_new ; Cs <- h_new
        lstm_update<<<2048, 256>>>(pGates, phC, pCs, NCLS);
        // CL_pre = Cs @ W_cl^T + b_cl                        (NCLS x 128)
        gemm_tn<<<dim3(D / BN, NCLS / BM), 256>>>(pCs, nullptr, nullptr, D, 0, 0,
                                                  W_cl, b_cl, pPre, D, D);
        // CL_msgs[l] = sum_{c in literal l} CL_pre[c]        (NLIT x 128)
        spmm_gather<<<NLIT, 128>>>(pLitPtr, pLitIdx, pPre, pMsgs);
        // gates_L = [msgs|L|hL] @ [WihL|WhhL]^T + (bih+bhh)  (NLIT x 512)
        gemm_tn<<<dim3(GD / BN, NLIT / BM), 256>>>(pMsgs, pL, phL, D, D, D,
                                                   pWL, pbL, pGates, GD, 3 * D);
        // hL <- c_new ; L <- h_new
        lstm_update<<<2048, 256>>>(pGates, phL, pL, NLIT);
    }

    copy_f<<<1024, 256>>>(out, pL, NLIT * D);
    (void)in_sizes; (void)n_in; (void)out_size;
}